// round 9
// baseline (speedup 1.0000x reference)
#include <cuda_runtime.h>
#include <cuda_fp16.h>
#include <cstdint>

#define N_NODES 50000
#define N_EDGES 1600000
#define IN_DIM 128
#define HID 64
#define N_GRAPHS 256
#define SLOTS 80                                   // fixed CSR row capacity (deg~Poisson(32))
#define GEMM_BLOCKS ((N_NODES + 63) / 64)          // 782
#define FILL_BLOCKS ((N_EDGES + 1023) / 1024)      // 1563 (4 edges/thread, 256 thr)

// -------- device scratch (no allocation allowed) --------
// lin has one extra zeroed dummy row at index N_NODES (target of CSR pad slots).
__device__ __align__(16) __half2 g_lin[(N_NODES + 1) * (HID / 2)];
__device__ float g_h[N_NODES * HID];               // fp32 buffer (gemm in/out)
__device__ int   g_edge[N_NODES * SLOTS];          // src indices, fixed stride per target
__device__ int   g_cnt[N_NODES];                   // degree counters (zeroed by prev launch)
__device__ float g_dinv[N_NODES];                  // rsqrt(deg+1)
__device__ float g_pool[N_GRAPHS * HID];           // (zeroed by prev launch)
__device__ float g_gcnt[N_GRAPHS];                 // (zeroed by prev launch)

// -------- GEMM body: 64x64 tile, 256 thr, 4x4/thread --------
__device__ __forceinline__ uint2 pack_half4(float4 a, float s) {
    __half2 lo = __floats2half2_rn(a.x * s, a.y * s);
    __half2 hi = __floats2half2_rn(a.z * s, a.w * s);
    uint2 u;
    u.x = reinterpret_cast<unsigned&>(lo);
    u.y = reinterpret_cast<unsigned&>(hi);
    return u;
}

// HALF_OUT: write lin (fp16, prescaled by dinv). else: write fp32 (unscaled).
template <int D, bool HALF_OUT>
__device__ __forceinline__ void gemm_body(int bid, int tid, const float* __restrict__ in,
                                          const float* __restrict__ W,
                                          const float* __restrict__ dinv,
                                          uint2* __restrict__ linout,
                                          float4* __restrict__ fout, int n) {
    constexpr int XS = D + 4;  // pad to avoid bank conflicts on broadcast x reads
    __shared__ float Xs[64 * XS];
    __shared__ float4 Ws4[D * 16];
    const float4* W4 = (const float4*)W;
    for (int i = tid; i < D * 16; i += 256) Ws4[i] = W4[i];
    int row0 = bid * 64;
    for (int i = tid; i < 64 * (D / 4); i += 256) {
        int r = i / (D / 4), c4 = i % (D / 4);
        float4 v = make_float4(0.f, 0.f, 0.f, 0.f);
        int gr = row0 + r;
        if (gr < n) v = ((const float4*)in)[(long)gr * (D / 4) + c4];
        *(float4*)&Xs[r * XS + c4 * 4] = v;
    }
    __syncthreads();
    int trow = tid >> 4, f4 = tid & 15;
    float4 a0 = make_float4(0.f, 0.f, 0.f, 0.f), a1 = a0, a2 = a0, a3 = a0;
    const float* x0p = &Xs[(trow * 4 + 0) * XS];
    const float* x1p = &Xs[(trow * 4 + 1) * XS];
    const float* x2p = &Xs[(trow * 4 + 2) * XS];
    const float* x3p = &Xs[(trow * 4 + 3) * XS];
#pragma unroll 8
    for (int k = 0; k < D; k++) {
        float4 wv = Ws4[k * 16 + f4];
        float x0 = x0p[k], x1 = x1p[k], x2 = x2p[k], x3 = x3p[k];
        a0.x += x0 * wv.x; a0.y += x0 * wv.y; a0.z += x0 * wv.z; a0.w += x0 * wv.w;
        a1.x += x1 * wv.x; a1.y += x1 * wv.y; a1.z += x1 * wv.z; a1.w += x1 * wv.w;
        a2.x += x2 * wv.x; a2.y += x2 * wv.y; a2.z += x2 * wv.z; a2.w += x2 * wv.w;
        a3.x += x3 * wv.x; a3.y += x3 * wv.y; a3.z += x3 * wv.z; a3.w += x3 * wv.w;
    }
    int r = row0 + trow * 4;
    if (HALF_OUT) {
        if (r + 0 < n) linout[(long)(r + 0) * 16 + f4] = pack_half4(a0, dinv[r + 0]);
        if (r + 1 < n) linout[(long)(r + 1) * 16 + f4] = pack_half4(a1, dinv[r + 1]);
        if (r + 2 < n) linout[(long)(r + 2) * 16 + f4] = pack_half4(a2, dinv[r + 2]);
        if (r + 3 < n) linout[(long)(r + 3) * 16 + f4] = pack_half4(a3, dinv[r + 3]);
    } else {
        if (r + 0 < n) fout[(long)(r + 0) * 16 + f4] = a0;
        if (r + 1 < n) fout[(long)(r + 1) * 16 + f4] = a1;
        if (r + 2 < n) fout[(long)(r + 2) * 16 + f4] = a2;
        if (r + 3 < n) fout[(long)(r + 3) * 16 + f4] = a3;
    }
}

// -------- kernel 1: fused layer-1 GEMM (fp32 out) + single-pass CSR fill --------
__global__ void gemm1_fill_kernel(const float* __restrict__ x, const float* __restrict__ W1,
                                  float4* __restrict__ hout,
                                  const int* __restrict__ row, const int* __restrict__ col,
                                  int* __restrict__ cnt, int* __restrict__ edges) {
    if (blockIdx.x < GEMM_BLOCKS) {
        gemm_body<IN_DIM, false>(blockIdx.x, threadIdx.x, x, W1, nullptr, nullptr, hout,
                                 N_NODES);
        return;
    }
    int i = (blockIdx.x - GEMM_BLOCKS) * 1024 + threadIdx.x * 4;
    if (i + 3 < N_EDGES) {
        int4 rr = *(const int4*)(row + i);
        int4 cc = *(const int4*)(col + i);
        if ((unsigned)rr.x < N_NODES && (unsigned)cc.x < N_NODES) {
            int p = atomicAdd(&cnt[cc.x], 1);
            if (p < SLOTS) edges[cc.x * SLOTS + p] = rr.x;
        }
        if ((unsigned)rr.y < N_NODES && (unsigned)cc.y < N_NODES) {
            int p = atomicAdd(&cnt[cc.y], 1);
            if (p < SLOTS) edges[cc.y * SLOTS + p] = rr.y;
        }
        if ((unsigned)rr.z < N_NODES && (unsigned)cc.z < N_NODES) {
            int p = atomicAdd(&cnt[cc.z], 1);
            if (p < SLOTS) edges[cc.z * SLOTS + p] = rr.z;
        }
        if ((unsigned)rr.w < N_NODES && (unsigned)cc.w < N_NODES) {
            int p = atomicAdd(&cnt[cc.w], 1);
            if (p < SLOTS) edges[cc.w * SLOTS + p] = rr.w;
        }
    } else {
        for (int u = 0; u < 4; u++) {
            int j = i + u;
            if (j < N_EDGES) {
                int r = row[j], c = col[j];
                if ((unsigned)r < N_NODES && (unsigned)c < N_NODES) {
                    int p = atomicAdd(&cnt[c], 1);
                    if (p < SLOTS) edges[c * SLOTS + p] = r;
                }
            }
        }
    }
}

// -------- kernel 2: finish — dinv, pad slots, lin = half(dinv*h), graph counts --------
// one warp per node
__global__ void finish_kernel(const int* __restrict__ cnt, float* __restrict__ dinv,
                              int* __restrict__ edges, const float2* __restrict__ h2,
                              __half2* __restrict__ lin2, const int* __restrict__ batch,
                              float* __restrict__ gcnt) {
    int node = (blockIdx.x * blockDim.x + threadIdx.x) >> 5;
    int lane = threadIdx.x & 31;
    if (node >= N_NODES) return;
    int d = cnt[node];
    if (d > SLOTS) d = SLOTS;
    float s = rsqrtf((float)(1 + d));
    if (lane == 0) {
        dinv[node] = s;
        int g = batch[node];
        if ((unsigned)g < N_GRAPHS) atomicAdd(&gcnt[g], 1.0f);
    }
    int pad = (d + 3) & ~3;
    if (lane < pad - d) edges[node * SLOTS + d + lane] = N_NODES;  // dummy (zero row)
    float2 v = h2[(long)node * 32 + lane];
    lin2[(long)node * 32 + lane] = __floats2half2_rn(s * v.x, s * v.y);
}

template <int D>
__global__ void gemm_kernel(const float* __restrict__ in, const float* __restrict__ W,
                            const float* __restrict__ dinv, uint2* __restrict__ lin, int n) {
    gemm_body<D, true>(blockIdx.x, threadIdx.x, in, W, dinv, lin, nullptr, n);
}

// -------- gather: out[c] = relu( dinv[c]*(sum_e lin'[src_e] + lin'[c]) + bias ) -------
// 8 threads per node (4 nodes/warp); each thread covers 8 features (uint4 = 4 half2);
// fp16 HADD2 accumulation in 4 slot-separated groups, fp32 combine.
template <bool POOL>
__global__ void gather_kernel(const uint4* __restrict__ lin4, const float* __restrict__ dinv,
                              const int* __restrict__ cnt, const int* __restrict__ edges,
                              const float4* __restrict__ bias4, float4* __restrict__ hout4,
                              const int* __restrict__ batch, float* __restrict__ pool) {
    int t = blockIdx.x * blockDim.x + threadIdx.x;
    int node = t >> 3;
    int sub = t & 7;           // feature octet: feats [sub*8, sub*8+8)
    if (node >= N_NODES) return;
    int d = cnt[node];
    if (d > SLOTS) d = SLOTS;
    int nq = (d + 3) >> 2;
    const int4* ep4 = (const int4*)(edges + node * SLOTS);
    __half2 z = __floats2half2_rn(0.f, 0.f);
    __half2 a0[4] = {z, z, z, z}, a1[4] = {z, z, z, z};
    __half2 a2[4] = {z, z, z, z}, a3[4] = {z, z, z, z};
#pragma unroll 2
    for (int j = 0; j < nq; j++) {
        int4 e = ep4[j];  // uniform across node-group -> broadcast
        uint4 v0 = lin4[(long)e.x * 8 + sub];
        uint4 v1 = lin4[(long)e.y * 8 + sub];
        uint4 v2 = lin4[(long)e.z * 8 + sub];
        uint4 v3 = lin4[(long)e.w * 8 + sub];
        a0[0] = __hadd2(a0[0], *(__half2*)&v0.x); a0[1] = __hadd2(a0[1], *(__half2*)&v0.y);
        a0[2] = __hadd2(a0[2], *(__half2*)&v0.z); a0[3] = __hadd2(a0[3], *(__half2*)&v0.w);
        a1[0] = __hadd2(a1[0], *(__half2*)&v1.x); a1[1] = __hadd2(a1[1], *(__half2*)&v1.y);
        a1[2] = __hadd2(a1[2], *(__half2*)&v1.z); a1[3] = __hadd2(a1[3], *(__half2*)&v1.w);
        a2[0] = __hadd2(a2[0], *(__half2*)&v2.x); a2[1] = __hadd2(a2[1], *(__half2*)&v2.y);
        a2[2] = __hadd2(a2[2], *(__half2*)&v2.z); a2[3] = __hadd2(a2[3], *(__half2*)&v2.w);
        a3[0] = __hadd2(a3[0], *(__half2*)&v3.x); a3[1] = __hadd2(a3[1], *(__half2*)&v3.y);
        a3[2] = __hadd2(a3[2], *(__half2*)&v3.z); a3[3] = __hadd2(a3[3], *(__half2*)&v3.w);
    }
    // self-loop (prescaled row)
    uint4 vs = lin4[(long)node * 8 + sub];
    float s = dinv[node];
    float4 bb0 = bias4[sub * 2], bb1 = bias4[sub * 2 + 1];
    float2 c0, c1, c2, c3, f0, f1, f2, f3;
    // combine feats 0..3
    f0 = __half22float2(a0[0]); f1 = __half22float2(a1[0]);
    f2 = __half22float2(a2[0]); f3 = __half22float2(a3[0]);
    c0.x = (f0.x + f1.x) + (f2.x + f3.x); c0.y = (f0.y + f1.y) + (f2.y + f3.y);
    f0 = __half22float2(a0[1]); f1 = __half22float2(a1[1]);
    f2 = __half22float2(a2[1]); f3 = __half22float2(a3[1]);
    c1.x = (f0.x + f1.x) + (f2.x + f3.x); c1.y = (f0.y + f1.y) + (f2.y + f3.y);
    f0 = __half22float2(a0[2]); f1 = __half22float2(a1[2]);
    f2 = __half22float2(a2[2]); f3 = __half22float2(a3[2]);
    c2.x = (f0.x + f1.x) + (f2.x + f3.x); c2.y = (f0.y + f1.y) + (f2.y + f3.y);
    f0 = __half22float2(a0[3]); f1 = __half22float2(a1[3]);
    f2 = __half22float2(a2[3]); f3 = __half22float2(a3[3]);
    c3.x = (f0.x + f1.x) + (f2.x + f3.x); c3.y = (f0.y + f1.y) + (f2.y + f3.y);
    float2 s0 = __half22float2(*(__half2*)&vs.x), s1 = __half22float2(*(__half2*)&vs.y);
    float2 s2 = __half22float2(*(__half2*)&vs.z), s3 = __half22float2(*(__half2*)&vs.w);
    float4 r0, r1;
    r0.x = fmaxf(fmaf(s, c0.x + s0.x, bb0.x), 0.f);
    r0.y = fmaxf(fmaf(s, c0.y + s0.y, bb0.y), 0.f);
    r0.z = fmaxf(fmaf(s, c1.x + s1.x, bb0.z), 0.f);
    r0.w = fmaxf(fmaf(s, c1.y + s1.y, bb0.w), 0.f);
    r1.x = fmaxf(fmaf(s, c2.x + s2.x, bb1.x), 0.f);
    r1.y = fmaxf(fmaf(s, c2.y + s2.y, bb1.y), 0.f);
    r1.z = fmaxf(fmaf(s, c3.x + s3.x, bb1.z), 0.f);
    r1.w = fmaxf(fmaf(s, c3.y + s3.y, bb1.w), 0.f);
    if (POOL) {
        int g = batch[node];
        if ((unsigned)g < N_GRAPHS) {
            float* dst = &pool[g * HID + sub * 8];
            atomicAdd(dst + 0, r0.x); atomicAdd(dst + 1, r0.y);
            atomicAdd(dst + 2, r0.z); atomicAdd(dst + 3, r0.w);
            atomicAdd(dst + 4, r1.x); atomicAdd(dst + 5, r1.y);
            atomicAdd(dst + 6, r1.z); atomicAdd(dst + 7, r1.w);
        }
    } else {
        hout4[(long)node * 16 + sub * 2] = r0;
        hout4[(long)node * 16 + sub * 2 + 1] = r1;
    }
}

// -------- final: MLP head (block 0) + zero cnt/pool/gcnt for next launch --------
__global__ void final_kernel(float* __restrict__ pool, float* __restrict__ gcnt,
                             const float* __restrict__ Wl1, const float* __restrict__ bl1,
                             const float* __restrict__ Wl2, const float* __restrict__ bl2,
                             float* __restrict__ out, int* __restrict__ cnt) {
    if (blockIdx.x > 0) {
        int j = (blockIdx.x - 1) * 256 + threadIdx.x;
        if (j < N_NODES) cnt[j] = 0;
        return;
    }
    int g = threadIdx.x;
    if (g >= N_GRAPHS) return;
    float c = gcnt[g];
    if (c < 1.0f) c = 1.0f;
    float inv = 1.0f / c;
    float gv[HID];
#pragma unroll
    for (int k = 0; k < HID; k++) gv[k] = pool[g * HID + k] * inv;
    float o = bl2[0];
#pragma unroll
    for (int j = 0; j < 16; j++) {
        float hj = bl1[j];
#pragma unroll
        for (int k = 0; k < HID; k++) hj += gv[k] * Wl1[k * 16 + j];
        o += hj * Wl2[j];
    }
    out[g] = o;
    // reset own state for next launch (each thread touches only its own row)
#pragma unroll
    for (int k = 0; k < HID; k++) pool[g * HID + k] = 0.0f;
    gcnt[g] = 0.0f;
}

extern "C" void kernel_launch(void* const* d_in, const int* in_sizes, int n_in,
                              void* d_out, int out_size) {
    const float* x   = (const float*)d_in[0];
    const int* ei    = (const int*)d_in[1];
    const int* batch = (const int*)d_in[2];
    const float* W1 = (const float*)d_in[3];
    const float* b1 = (const float*)d_in[4];
    const float* W2 = (const float*)d_in[5];
    const float* b2 = (const float*)d_in[6];
    const float* W3 = (const float*)d_in[7];
    const float* b3 = (const float*)d_in[8];
    const float* Wl1 = (const float*)d_in[9];
    const float* bl1 = (const float*)d_in[10];
    const float* Wl2 = (const float*)d_in[11];
    const float* bl2 = (const float*)d_in[12];
    float* out = (float*)d_out;

    const int* row = ei;
    const int* col = ei + N_EDGES;

    static __half2* p_lin = nullptr;
    static float *p_h = nullptr, *p_dinv = nullptr, *p_pool = nullptr, *p_gcnt = nullptr;
    static int *p_cnt = nullptr, *p_edge = nullptr;
    if (!p_lin) {
        cudaGetSymbolAddress((void**)&p_lin, g_lin);
        cudaGetSymbolAddress((void**)&p_h, g_h);
        cudaGetSymbolAddress((void**)&p_dinv, g_dinv);
        cudaGetSymbolAddress((void**)&p_pool, g_pool);
        cudaGetSymbolAddress((void**)&p_gcnt, g_gcnt);
        cudaGetSymbolAddress((void**)&p_cnt, g_cnt);
        cudaGetSymbolAddress((void**)&p_edge, g_edge);
    }

    const int n = N_NODES;
    int gath_blocks = (n * 8 + 255) / 256;
    int warp_blocks = (n * 32 + 255) / 256;

    // 1. layer-1 GEMM (fp32 out) fused with single-pass CSR fill (cnt pre-zeroed)
    gemm1_fill_kernel<<<GEMM_BLOCKS + FILL_BLOCKS, 256>>>(x, W1, (float4*)p_h, row, col,
                                                          p_cnt, p_edge);
    // 2. dinv + pad slots + lin = half(dinv*h) + graph counts
    finish_kernel<<<warp_blocks, 256>>>(p_cnt, p_dinv, p_edge, (const float2*)p_h, p_lin,
                                        batch, p_gcnt);
    // Layer 1 aggregate
    gather_kernel<false><<<gath_blocks, 256>>>((const uint4*)p_lin, p_dinv, p_cnt, p_edge,
                                               (const float4*)b1, (float4*)p_h, batch, p_pool);
    // Layer 2
    gemm_kernel<HID><<<GEMM_BLOCKS, 256>>>(p_h, W2, p_dinv, (uint2*)p_lin, n);
    gather_kernel<false><<<gath_blocks, 256>>>((const uint4*)p_lin, p_dinv, p_cnt, p_edge,
                                               (const float4*)b2, (float4*)p_h, batch, p_pool);
    // Layer 3 (fused pooling)
    gemm_kernel<HID><<<GEMM_BLOCKS, 256>>>(p_h, W3, p_dinv, (uint2*)p_lin, n);
    gather_kernel<true><<<gath_blocks, 256>>>((const uint4*)p_lin, p_dinv, p_cnt, p_edge,
                                              (const float4*)b3, nullptr, batch, p_pool);
    // Head + reset state for next launch
    final_kernel<<<1 + (n + 255) / 256, 256>>>(p_pool, p_gcnt, Wl1, bl1, Wl2, bl2, out, p_cnt);
}

// round 11
// speedup vs baseline: 1.1181x; 1.1181x over previous
#include <cuda_runtime.h>
#include <cuda_fp16.h>
#include <cstdint>

#define N_NODES 50000
#define N_EDGES 1600000
#define IN_DIM 128
#define HID 64
#define N_GRAPHS 256
#define SLOTS 80                                   // fixed CSR row capacity (deg~Poisson(32))
#define GEMM_BLOCKS ((N_NODES + 63) / 64)          // 782
#define FILL_BLOCKS ((N_EDGES + 1023) / 1024)      // 1563 (4 edges/thread, 256 thr)

// -------- device scratch (no allocation allowed) --------
// lin has one extra zeroed dummy row at index N_NODES (target of CSR pad slots).
__device__ __align__(16) __half2 g_lin[(N_NODES + 1) * (HID / 2)];
__device__ float g_h[N_NODES * HID];               // fp32 buffer (gemm in/out)
__device__ int   g_edge[N_NODES * SLOTS];          // src indices, fixed stride per target
__device__ int   g_cnt[N_NODES];                   // degree counters (zeroed by prev launch)
__device__ float g_dinv[N_NODES];                  // rsqrt(deg+1)
__device__ float g_pool[N_GRAPHS * HID];           // (zeroed by prev launch)
__device__ float g_gcnt[N_GRAPHS];                 // (zeroed by prev launch)

// -------- GEMM body: 64x64 tile, 256 thr, 4x4/thread, k-chunked (float4 x loads) ------
__device__ __forceinline__ uint2 pack_half4(float4 a, float s) {
    __half2 lo = __floats2half2_rn(a.x * s, a.y * s);
    __half2 hi = __floats2half2_rn(a.z * s, a.w * s);
    uint2 u;
    u.x = reinterpret_cast<unsigned&>(lo);
    u.y = reinterpret_cast<unsigned&>(hi);
    return u;
}

// HALF_OUT: write lin (fp16, prescaled by dinv). else: write fp32 (unscaled).
template <int D, bool HALF_OUT>
__device__ __forceinline__ void gemm_body(int bid, int tid, const float* __restrict__ in,
                                          const float* __restrict__ W,
                                          const float* __restrict__ dinv,
                                          uint2* __restrict__ linout,
                                          float4* __restrict__ fout, int n) {
    constexpr int XS = D + 4;  // pad (16B-aligned rows, spreads banks)
    __shared__ float Xs[64 * XS];
    __shared__ float4 Ws4[D * 16];
    const float4* W4 = (const float4*)W;
    for (int i = tid; i < D * 16; i += 256) Ws4[i] = W4[i];
    int row0 = bid * 64;
    for (int i = tid; i < 64 * (D / 4); i += 256) {
        int r = i / (D / 4), c4 = i % (D / 4);
        float4 v = make_float4(0.f, 0.f, 0.f, 0.f);
        int gr = row0 + r;
        if (gr < n) v = ((const float4*)in)[(long)gr * (D / 4) + c4];
        *(float4*)&Xs[r * XS + c4 * 4] = v;
    }
    __syncthreads();
    int trow = tid >> 4, f4 = tid & 15;
    float4 a0 = make_float4(0.f, 0.f, 0.f, 0.f), a1 = a0, a2 = a0, a3 = a0;
    const float* x0p = &Xs[(trow * 4 + 0) * XS];
    const float* x1p = &Xs[(trow * 4 + 1) * XS];
    const float* x2p = &Xs[(trow * 4 + 2) * XS];
    const float* x3p = &Xs[(trow * 4 + 3) * XS];
#pragma unroll
    for (int kc = 0; kc < D / 4; kc++) {
        float4 x0 = *(const float4*)&x0p[kc * 4];
        float4 x1 = *(const float4*)&x1p[kc * 4];
        float4 x2 = *(const float4*)&x2p[kc * 4];
        float4 x3 = *(const float4*)&x3p[kc * 4];
        float4 w0 = Ws4[(kc * 4 + 0) * 16 + f4];
        float4 w1 = Ws4[(kc * 4 + 1) * 16 + f4];
        float4 w2 = Ws4[(kc * 4 + 2) * 16 + f4];
        float4 w3 = Ws4[(kc * 4 + 3) * 16 + f4];
        a0.x += x0.x * w0.x + x0.y * w1.x + x0.z * w2.x + x0.w * w3.x;
        a0.y += x0.x * w0.y + x0.y * w1.y + x0.z * w2.y + x0.w * w3.y;
        a0.z += x0.x * w0.z + x0.y * w1.z + x0.z * w2.z + x0.w * w3.z;
        a0.w += x0.x * w0.w + x0.y * w1.w + x0.z * w2.w + x0.w * w3.w;
        a1.x += x1.x * w0.x + x1.y * w1.x + x1.z * w2.x + x1.w * w3.x;
        a1.y += x1.x * w0.y + x1.y * w1.y + x1.z * w2.y + x1.w * w3.y;
        a1.z += x1.x * w0.z + x1.y * w1.z + x1.z * w2.z + x1.w * w3.z;
        a1.w += x1.x * w0.w + x1.y * w1.w + x1.z * w2.w + x1.w * w3.w;
        a2.x += x2.x * w0.x + x2.y * w1.x + x2.z * w2.x + x2.w * w3.x;
        a2.y += x2.x * w0.y + x2.y * w1.y + x2.z * w2.y + x2.w * w3.y;
        a2.z += x2.x * w0.z + x2.y * w1.z + x2.z * w2.z + x2.w * w3.z;
        a2.w += x2.x * w0.w + x2.y * w1.w + x2.z * w2.w + x2.w * w3.w;
        a3.x += x3.x * w0.x + x3.y * w1.x + x3.z * w2.x + x3.w * w3.x;
        a3.y += x3.x * w0.y + x3.y * w1.y + x3.z * w2.y + x3.w * w3.y;
        a3.z += x3.x * w0.z + x3.y * w1.z + x3.z * w2.z + x3.w * w3.z;
        a3.w += x3.x * w0.w + x3.y * w1.w + x3.z * w2.w + x3.w * w3.w;
    }
    int r = row0 + trow * 4;
    if (HALF_OUT) {
        if (r + 0 < n) linout[(long)(r + 0) * 16 + f4] = pack_half4(a0, dinv[r + 0]);
        if (r + 1 < n) linout[(long)(r + 1) * 16 + f4] = pack_half4(a1, dinv[r + 1]);
        if (r + 2 < n) linout[(long)(r + 2) * 16 + f4] = pack_half4(a2, dinv[r + 2]);
        if (r + 3 < n) linout[(long)(r + 3) * 16 + f4] = pack_half4(a3, dinv[r + 3]);
    } else {
        if (r + 0 < n) fout[(long)(r + 0) * 16 + f4] = a0;
        if (r + 1 < n) fout[(long)(r + 1) * 16 + f4] = a1;
        if (r + 2 < n) fout[(long)(r + 2) * 16 + f4] = a2;
        if (r + 3 < n) fout[(long)(r + 3) * 16 + f4] = a3;
    }
}

// -------- kernel 1: fused layer-1 GEMM (fp32 out) + single-pass CSR fill --------
__global__ void gemm1_fill_kernel(const float* __restrict__ x, const float* __restrict__ W1,
                                  float4* __restrict__ hout,
                                  const int* __restrict__ row, const int* __restrict__ col,
                                  int* __restrict__ cnt, int* __restrict__ edges) {
    if (blockIdx.x < GEMM_BLOCKS) {
        gemm_body<IN_DIM, false>(blockIdx.x, threadIdx.x, x, W1, nullptr, nullptr, hout,
                                 N_NODES);
        return;
    }
    int i = (blockIdx.x - GEMM_BLOCKS) * 1024 + threadIdx.x * 4;
    if (i + 3 < N_EDGES) {
        int4 rr = *(const int4*)(row + i);
        int4 cc = *(const int4*)(col + i);
        if ((unsigned)rr.x < N_NODES && (unsigned)cc.x < N_NODES) {
            int p = atomicAdd(&cnt[cc.x], 1);
            if (p < SLOTS) edges[cc.x * SLOTS + p] = rr.x;
        }
        if ((unsigned)rr.y < N_NODES && (unsigned)cc.y < N_NODES) {
            int p = atomicAdd(&cnt[cc.y], 1);
            if (p < SLOTS) edges[cc.y * SLOTS + p] = rr.y;
        }
        if ((unsigned)rr.z < N_NODES && (unsigned)cc.z < N_NODES) {
            int p = atomicAdd(&cnt[cc.z], 1);
            if (p < SLOTS) edges[cc.z * SLOTS + p] = rr.z;
        }
        if ((unsigned)rr.w < N_NODES && (unsigned)cc.w < N_NODES) {
            int p = atomicAdd(&cnt[cc.w], 1);
            if (p < SLOTS) edges[cc.w * SLOTS + p] = rr.w;
        }
    } else {
        for (int u = 0; u < 4; u++) {
            int j = i + u;
            if (j < N_EDGES) {
                int r = row[j], c = col[j];
                if ((unsigned)r < N_NODES && (unsigned)c < N_NODES) {
                    int p = atomicAdd(&cnt[c], 1);
                    if (p < SLOTS) edges[c * SLOTS + p] = r;
                }
            }
        }
    }
}

// -------- kernel 2: finish — dinv, pad slots, lin = half(dinv*h), graph counts --------
// one warp per node
__global__ void finish_kernel(const int* __restrict__ cnt, float* __restrict__ dinv,
                              int* __restrict__ edges, const float2* __restrict__ h2,
                              __half2* __restrict__ lin2, const int* __restrict__ batch,
                              float* __restrict__ gcnt) {
    int node = (blockIdx.x * blockDim.x + threadIdx.x) >> 5;
    int lane = threadIdx.x & 31;
    if (node >= N_NODES) return;
    int d = cnt[node];
    if (d > SLOTS) d = SLOTS;
    float s = rsqrtf((float)(1 + d));
    if (lane == 0) {
        dinv[node] = s;
        int g = batch[node];
        if ((unsigned)g < N_GRAPHS) atomicAdd(&gcnt[g], 1.0f);
    }
    int pad = (d + 3) & ~3;
    if (lane < pad - d) edges[node * SLOTS + d + lane] = N_NODES;  // dummy (zero row)
    float2 v = h2[(long)node * 32 + lane];
    lin2[(long)node * 32 + lane] = __floats2half2_rn(s * v.x, s * v.y);
}

template <int D>
__global__ void gemm_kernel(const float* __restrict__ in, const float* __restrict__ W,
                            const float* __restrict__ dinv, uint2* __restrict__ lin, int n) {
    gemm_body<D, true>(blockIdx.x, threadIdx.x, in, W, dinv, lin, nullptr, n);
}

// -------- gather: out[c] = relu( dinv[c]*(sum_e lin'[src_e] + lin'[c]) + bias ) -------
// half-warp per node (2 nodes/warp); lane covers 4 features (uint2 = 2 half2);
// fp16 HADD2 accumulation in 4 slot-separated accumulators, fp32 combine. (R8 layout)
template <bool POOL>
__global__ void gather_kernel(const uint2* __restrict__ lin2, const float* __restrict__ dinv,
                              const int* __restrict__ cnt, const int* __restrict__ edges,
                              const float4* __restrict__ bias4, float4* __restrict__ hout4,
                              const int* __restrict__ batch, float* __restrict__ pool) {
    int t = blockIdx.x * blockDim.x + threadIdx.x;
    int node = t >> 4;
    int sub = t & 15;          // feature quad: feats [sub*4, sub*4+4)
    if (node >= N_NODES) return;
    int d = cnt[node];
    if (d > SLOTS) d = SLOTS;
    int nq = (d + 3) >> 2;
    const int4* ep4 = (const int4*)(edges + node * SLOTS);
    __half2 zero = __floats2half2_rn(0.f, 0.f);
    __half2 al0 = zero, al1 = zero, al2 = zero, al3 = zero;
    __half2 ah0 = zero, ah1 = zero, ah2 = zero, ah3 = zero;
#pragma unroll 2
    for (int j = 0; j < nq; j++) {
        int4 e = ep4[j];  // uniform across half-warp -> broadcast
        uint2 v0 = lin2[(long)e.x * 16 + sub];
        uint2 v1 = lin2[(long)e.y * 16 + sub];
        uint2 v2 = lin2[(long)e.z * 16 + sub];
        uint2 v3 = lin2[(long)e.w * 16 + sub];
        al0 = __hadd2(al0, *(__half2*)&v0.x); ah0 = __hadd2(ah0, *(__half2*)&v0.y);
        al1 = __hadd2(al1, *(__half2*)&v1.x); ah1 = __hadd2(ah1, *(__half2*)&v1.y);
        al2 = __hadd2(al2, *(__half2*)&v2.x); ah2 = __hadd2(ah2, *(__half2*)&v2.y);
        al3 = __hadd2(al3, *(__half2*)&v3.x); ah3 = __hadd2(ah3, *(__half2*)&v3.y);
    }
    float2 lo0 = __half22float2(al0), lo1 = __half22float2(al1);
    float2 lo2 = __half22float2(al2), lo3 = __half22float2(al3);
    float2 hi0 = __half22float2(ah0), hi1 = __half22float2(ah1);
    float2 hi2 = __half22float2(ah2), hi3 = __half22float2(ah3);
    float sx = (lo0.x + lo1.x) + (lo2.x + lo3.x);
    float sy = (lo0.y + lo1.y) + (lo2.y + lo3.y);
    float sz = (hi0.x + hi1.x) + (hi2.x + hi3.x);
    float sw = (hi0.y + hi1.y) + (hi2.y + hi3.y);
    uint2 vs = lin2[(long)node * 16 + sub];  // self-loop (prescaled row)
    float2 vsl = __half22float2(*(__half2*)&vs.x);
    float2 vsh = __half22float2(*(__half2*)&vs.y);
    sx += vsl.x; sy += vsl.y; sz += vsh.x; sw += vsh.y;
    float s = dinv[node];
    float4 bb = bias4[sub];
    float4 r;
    r.x = fmaxf(fmaf(s, sx, bb.x), 0.f);
    r.y = fmaxf(fmaf(s, sy, bb.y), 0.f);
    r.z = fmaxf(fmaf(s, sz, bb.z), 0.f);
    r.w = fmaxf(fmaf(s, sw, bb.w), 0.f);
    if (POOL) {
        int g = batch[node];
        if ((unsigned)g < N_GRAPHS) {
            float* dst = &pool[g * HID + sub * 4];
            atomicAdd(dst + 0, r.x);
            atomicAdd(dst + 1, r.y);
            atomicAdd(dst + 2, r.z);
            atomicAdd(dst + 3, r.w);
        }
    } else {
        hout4[(long)node * 16 + sub] = r;
    }
}

// -------- final: MLP head (block 0) + zero cnt/pool/gcnt for next launch --------
__global__ void final_kernel(float* __restrict__ pool, float* __restrict__ gcnt,
                             const float* __restrict__ Wl1, const float* __restrict__ bl1,
                             const float* __restrict__ Wl2, const float* __restrict__ bl2,
                             float* __restrict__ out, int* __restrict__ cnt) {
    if (blockIdx.x > 0) {
        int j = (blockIdx.x - 1) * 256 + threadIdx.x;
        if (j < N_NODES) cnt[j] = 0;
        return;
    }
    int g = threadIdx.x;
    if (g >= N_GRAPHS) return;
    float c = gcnt[g];
    if (c < 1.0f) c = 1.0f;
    float inv = 1.0f / c;
    float gv[HID];
#pragma unroll
    for (int k = 0; k < HID; k++) gv[k] = pool[g * HID + k] * inv;
    float o = bl2[0];
#pragma unroll
    for (int j = 0; j < 16; j++) {
        float hj = bl1[j];
#pragma unroll
        for (int k = 0; k < HID; k++) hj += gv[k] * Wl1[k * 16 + j];
        o += hj * Wl2[j];
    }
    out[g] = o;
    // reset own state for next launch (each thread touches only its own row)
#pragma unroll
    for (int k = 0; k < HID; k++) pool[g * HID + k] = 0.0f;
    gcnt[g] = 0.0f;
}

extern "C" void kernel_launch(void* const* d_in, const int* in_sizes, int n_in,
                              void* d_out, int out_size) {
    const float* x   = (const float*)d_in[0];
    const int* ei    = (const int*)d_in[1];
    const int* batch = (const int*)d_in[2];
    const float* W1 = (const float*)d_in[3];
    const float* b1 = (const float*)d_in[4];
    const float* W2 = (const float*)d_in[5];
    const float* b2 = (const float*)d_in[6];
    const float* W3 = (const float*)d_in[7];
    const float* b3 = (const float*)d_in[8];
    const float* Wl1 = (const float*)d_in[9];
    const float* bl1 = (const float*)d_in[10];
    const float* Wl2 = (const float*)d_in[11];
    const float* bl2 = (const float*)d_in[12];
    float* out = (float*)d_out;

    const int* row = ei;
    const int* col = ei + N_EDGES;

    static __half2* p_lin = nullptr;
    static float *p_h = nullptr, *p_dinv = nullptr, *p_pool = nullptr, *p_gcnt = nullptr;
    static int *p_cnt = nullptr, *p_edge = nullptr;
    if (!p_lin) {
        cudaGetSymbolAddress((void**)&p_lin, g_lin);
        cudaGetSymbolAddress((void**)&p_h, g_h);
        cudaGetSymbolAddress((void**)&p_dinv, g_dinv);
        cudaGetSymbolAddress((void**)&p_pool, g_pool);
        cudaGetSymbolAddress((void**)&p_gcnt, g_gcnt);
        cudaGetSymbolAddress((void**)&p_cnt, g_cnt);
        cudaGetSymbolAddress((void**)&p_edge, g_edge);
    }

    const int n = N_NODES;
    int gath_blocks = (n * 16 + 255) / 256;
    int warp_blocks = (n * 32 + 255) / 256;

    // 1. layer-1 GEMM (fp32 out) fused with single-pass CSR fill (cnt pre-zeroed)
    gemm1_fill_kernel<<<GEMM_BLOCKS + FILL_BLOCKS, 256>>>(x, W1, (float4*)p_h, row, col,
                                                          p_cnt, p_edge);
    // 2. dinv + pad slots + lin = half(dinv*h) + graph counts
    finish_kernel<<<warp_blocks, 256>>>(p_cnt, p_dinv, p_edge, (const float2*)p_h, p_lin,
                                        batch, p_gcnt);
    // Layer 1 aggregate
    gather_kernel<false><<<gath_blocks, 256>>>((const uint2*)p_lin, p_dinv, p_cnt, p_edge,
                                               (const float4*)b1, (float4*)p_h, batch, p_pool);
    // Layer 2
    gemm_kernel<HID><<<GEMM_BLOCKS, 256>>>(p_h, W2, p_dinv, (uint2*)p_lin, n);
    gather_kernel<false><<<gath_blocks, 256>>>((const uint2*)p_lin, p_dinv, p_cnt, p_edge,
                                               (const float4*)b2, (float4*)p_h, batch, p_pool);
    // Layer 3 (fused pooling)
    gemm_kernel<HID><<<GEMM_BLOCKS, 256>>>(p_h, W3, p_dinv, (uint2*)p_lin, n);
    gather_kernel<true><<<gath_blocks, 256>>>((const uint2*)p_lin, p_dinv, p_cnt, p_edge,
                                              (const float4*)b3, nullptr, batch, p_pool);
    // Head + reset state for next launch
    final_kernel<<<1 + (n + 255) / 256, 256>>>(p_pool, p_gcnt, Wl1, bl1, Wl2, bl2, out, p_cnt);
}